// round 8
// baseline (speedup 1.0000x reference)
#include <cuda_runtime.h>
#include <cuda_fp16.h>
#include <math.h>
#include <stdint.h>

#define KCODES 512
#define CDIM   64
#define NPIX   131072
#define HW     4096
#define CHW    262144
#define TILE_M 128
#define NT     (NPIX/TILE_M)    // 1024 tiles
#define GRID   296              // 2 CTAs/SM persistent
#define CBP    72               // fp16 B row pad (144B, conflict-free ldmatrix)
#define XNP    68               // fp32 xn row pad (272B)
#define CAP    7
#define MARGIN 4e-3f

// __device__ scratch (allocation-free rule)
__device__ float g_cbn[KCODES*CDIM];   // normalized codebook fp32
__device__ __half g_cbh[KCODES*CDIM];  // normalized codebook fp16
__device__ float g_cc[KCODES];         // ||cbn_k||^2

// ---------------- smem layout (112 KB -> 2 CTAs/SM) ----------------
#define OFF_B    0                 // 512*72*2 = 73728
#define OFF_XN   73728             // 128*68*4 = 34816
#define OFF_CC   108544            // 2048
#define OFF_LIST 110592            // 128*7*4  = 3584
#define OFF_CNT  114176            // 512
#define SM_TOTAL 114688

// ---------------- helpers ----------------
__device__ __forceinline__ uint32_t smem_u32(const void* p) {
    uint32_t a;
    asm("{ .reg .u64 t; cvta.to.shared.u64 t, %1; cvt.u32.u64 %0, t; }" : "=r"(a) : "l"(p));
    return a;
}
__device__ __forceinline__ void ldsm4(uint32_t* r, uint32_t addr) {
    asm volatile("ldmatrix.sync.aligned.m8n8.x4.shared.b16 {%0,%1,%2,%3}, [%4];"
                 : "=r"(r[0]), "=r"(r[1]), "=r"(r[2]), "=r"(r[3]) : "r"(addr));
}
__device__ __forceinline__ void mma16816(float* c, const uint32_t* a,
                                         uint32_t b0, uint32_t b1) {
    asm volatile("mma.sync.aligned.m16n8k16.row.col.f32.f16.f16.f32 "
                 "{%0,%1,%2,%3}, {%4,%5,%6,%7}, {%8,%9}, {%0,%1,%2,%3};"
                 : "+f"(c[0]), "+f"(c[1]), "+f"(c[2]), "+f"(c[3])
                 : "r"(a[0]), "r"(a[1]), "r"(a[2]), "r"(a[3]), "r"(b0), "r"(b1));
}
__device__ __forceinline__ uint32_t h2(float lo, float hi) {
    __half2 v = __floats2half2_rn(lo, hi);
    return *(uint32_t*)&v;
}

// ---------------------------------------------------------------------------
// Prep: normalize codebook -> fp32 + fp16 copies + ||c||^2
// ---------------------------------------------------------------------------
__global__ void prep_kernel(const float* __restrict__ cb) {
    int k = blockIdx.x * blockDim.x + threadIdx.x;
    if (k >= KCODES) return;
    float row[CDIM];
    float ss = 0.f;
    #pragma unroll
    for (int c = 0; c < CDIM; ++c) { row[c] = cb[k*CDIM + c]; ss += row[c]*row[c]; }
    float inv = 1.0f / fmaxf(sqrtf(ss), 1e-12f);
    float cc = 0.f;
    #pragma unroll
    for (int c = 0; c < CDIM; ++c) {
        float v = row[c] * inv;
        g_cbn[k*CDIM + c] = v;
        g_cbh[k*CDIM + c] = __float2half_rn(v);
        cc += v*v;
    }
    g_cc[k] = cc;
}

// ---------------------------------------------------------------------------
// Main: persistent, 2 CTAs/SM, slim register blocking (C[2][4] per n-tile of
// 16 codes) so the 128-reg cap is met WITHOUT spills.
// ---------------------------------------------------------------------------
__global__ void __launch_bounds__(256, 2)
vq_kernel(const float* __restrict__ x, float* __restrict__ out, int write_idx) {
    extern __shared__ char sm[];
    __half* Bh = (__half*)(sm + OFF_B);
    float*  XN = (float*)(sm + OFF_XN);
    float*  CC = (float*)(sm + OFF_CC);
    int*  LIST = (int*)(sm + OFF_LIST);
    int*   CNT = (int*)(sm + OFF_CNT);

    int tid = threadIdx.x, lane = tid & 31, wid = tid >> 5;

    // ---- one-time: fp16 codebook + cc into smem ----
    {
        const uint4* src = (const uint4*)g_cbh;   // 4096 x 16B
        #pragma unroll 4
        for (int i = tid; i < 4096; i += 256) {
            int n = i >> 3, q = i & 7;
            *(uint4*)(Bh + n*CBP + q*8) = src[i];
        }
        for (int i = tid; i < KCODES; i += 256) CC[i] = g_cc[i];
    }

    uint32_t smb = smem_u32(sm);
    uint32_t BhB = smb + OFF_B;

    for (int tile = blockIdx.x; tile < NT; tile += GRID) {
        __syncthreads();   // previous tile fully consumed
        if (tid < TILE_M) CNT[tid] = 0;

        // ---- load + normalize x into XN (2 threads per row) ----
        {
            int r = tid >> 1, hc = (tid & 1) * 32;
            int n = tile*TILE_M + r;
            const float* xb = x + (size_t)(n >> 12)*CHW + (n & 4095);
            float v[32];
            float ss = 0.f;
            #pragma unroll
            for (int i = 0; i < 32; ++i) { v[i] = xb[(size_t)(hc+i)*HW]; ss += v[i]*v[i]; }
            ss += __shfl_xor_sync(0xffffffffu, ss, 1);
            float inv = 1.0f / fmaxf(sqrtf(ss), 1e-12f);
            #pragma unroll
            for (int i = 0; i < 32; ++i) XN[r*XNP + hc + i] = v[i] * inv;
        }
        __syncthreads();

        // ---- GEMM prune: warp w rows 16w..16w+15, 32 n-tiles of 16 codes ----
        {
            int r0 = wid * 16;
            // A fragments from fp32 XN (m16n8k16 layout), built once per tile
            uint32_t a[4][4];
            {
                int r = lane >> 2, c2 = (lane & 3) * 2;
                const float* xr0 = XN + (r0 + r)*XNP;
                const float* xr8 = xr0 + 8*XNP;
                #pragma unroll
                for (int j = 0; j < 4; ++j) {
                    float2 v0 = *(const float2*)(xr0 + 16*j + c2);
                    float2 v1 = *(const float2*)(xr8 + 16*j + c2);
                    float2 v2 = *(const float2*)(xr0 + 16*j + 8 + c2);
                    float2 v3 = *(const float2*)(xr8 + 16*j + 8 + c2);
                    a[j][0] = h2(v0.x, v0.y);
                    a[j][1] = h2(v1.x, v1.y);
                    a[j][2] = h2(v2.x, v2.y);
                    a[j][3] = h2(v3.x, v3.y);
                }
            }
            int noff = (lane & 7) + ((lane >> 4) << 3);
            int kadd = ((lane >> 3) & 1) << 3;
            int row_lo = r0 + (lane >> 2), row_hi = row_lo + 8;
            float best_lo = 1e30f, best_hi = 1e30f;
            uint32_t baseB = BhB + (uint32_t)((noff*CBP + kadd) * 2);

            for (int nt = 0; nt < 32; ++nt) {
                float C0[4] = {0.f, 0.f, 0.f, 0.f};
                float C1[4] = {0.f, 0.f, 0.f, 0.f};
                uint32_t bad = baseB + (uint32_t)(nt * (16*CBP*2));
                #pragma unroll
                for (int j = 0; j < 4; ++j) {
                    uint32_t b[4];
                    ldsm4(b, bad + 32u*j);
                    mma16816(C0, a[j], b[0], b[1]);
                    mma16816(C1, a[j], b[2], b[3]);
                }
                int c0 = nt*16 + 2*(lane & 3);
                int c1 = c0 + 8;
                float cc00 = CC[c0], cc01 = CC[c0+1];
                float cc10 = CC[c1], cc11 = CC[c1+1];
                C0[0] = fmaf(-2.f, C0[0], cc00);
                C0[1] = fmaf(-2.f, C0[1], cc01);
                C0[2] = fmaf(-2.f, C0[2], cc00);
                C0[3] = fmaf(-2.f, C0[3], cc01);
                C1[0] = fmaf(-2.f, C1[0], cc10);
                C1[1] = fmaf(-2.f, C1[1], cc11);
                C1[2] = fmaf(-2.f, C1[2], cc10);
                C1[3] = fmaf(-2.f, C1[3], cc11);
                best_lo = fminf(best_lo, fminf(fminf(C0[0], C0[1]), fminf(C1[0], C1[1])));
                best_hi = fminf(best_hi, fminf(fminf(C0[2], C0[3]), fminf(C1[2], C1[3])));
                best_lo = fminf(best_lo, __shfl_xor_sync(0xffffffffu, best_lo, 1));
                best_lo = fminf(best_lo, __shfl_xor_sync(0xffffffffu, best_lo, 2));
                best_hi = fminf(best_hi, __shfl_xor_sync(0xffffffffu, best_hi, 1));
                best_hi = fminf(best_hi, __shfl_xor_sync(0xffffffffu, best_hi, 2));
                float thr_lo = best_lo + MARGIN, thr_hi = best_hi + MARGIN;

                if (C0[0] <= thr_lo) { int p = atomicAdd(&CNT[row_lo], 1); if (p < CAP) LIST[row_lo*CAP + p] = c0;   }
                if (C0[1] <= thr_lo) { int p = atomicAdd(&CNT[row_lo], 1); if (p < CAP) LIST[row_lo*CAP + p] = c0+1; }
                if (C1[0] <= thr_lo) { int p = atomicAdd(&CNT[row_lo], 1); if (p < CAP) LIST[row_lo*CAP + p] = c1;   }
                if (C1[1] <= thr_lo) { int p = atomicAdd(&CNT[row_lo], 1); if (p < CAP) LIST[row_lo*CAP + p] = c1+1; }
                if (C0[2] <= thr_hi) { int p = atomicAdd(&CNT[row_hi], 1); if (p < CAP) LIST[row_hi*CAP + p] = c0;   }
                if (C0[3] <= thr_hi) { int p = atomicAdd(&CNT[row_hi], 1); if (p < CAP) LIST[row_hi*CAP + p] = c0+1; }
                if (C1[2] <= thr_hi) { int p = atomicAdd(&CNT[row_hi], 1); if (p < CAP) LIST[row_hi*CAP + p] = c1;   }
                if (C1[3] <= thr_hi) { int p = atomicAdd(&CNT[row_hi], 1); if (p < CAP) LIST[row_hi*CAP + p] = c1+1; }
            }
        }
        __syncthreads();

        // ---- exact fp32 rescore (2 threads/row) + output ----
        {
            int r = tid >> 1, par = tid & 1;
            int n = tile*TILE_M + r;
            int cn = CNT[r];
            bool ovf = (cn > CAP);
            if (cn > CAP) cn = CAP;

            const float4* x4 = (const float4*)(XN + r*XNP);
            float bd = 1e30f;
            int   bk = 0x7fffffff;

            if (!ovf) {
                for (int i = par; i < cn; i += 2) {
                    int k = LIST[r*CAP + i];
                    const float4* cb4 = (const float4*)(g_cbn + (size_t)k*CDIM);
                    float d0 = 0.f, d1 = 0.f;
                    #pragma unroll
                    for (int q = 0; q < 16; q += 2) {
                        float4 xa = x4[q],   ca = cb4[q];
                        float4 xb2 = x4[q+1], cb2 = cb4[q+1];
                        d0 = fmaf(xa.x, ca.x, d0);  d0 = fmaf(xa.y, ca.y, d0);
                        d0 = fmaf(xa.z, ca.z, d0);  d0 = fmaf(xa.w, ca.w, d0);
                        d1 = fmaf(xb2.x, cb2.x, d1); d1 = fmaf(xb2.y, cb2.y, d1);
                        d1 = fmaf(xb2.z, cb2.z, d1); d1 = fmaf(xb2.w, cb2.w, d1);
                    }
                    float d = fmaf(-2.f, d0 + d1, CC[k]);
                    if (d < bd || (d == bd && k < bk)) { bd = d; bk = k; }
                }
            } else {
                for (int k = par; k < KCODES; k += 2) {
                    const float4* cb4 = (const float4*)(g_cbn + (size_t)k*CDIM);
                    float d0 = 0.f;
                    #pragma unroll
                    for (int q = 0; q < 16; ++q) {
                        float4 xa = x4[q], ca = cb4[q];
                        d0 = fmaf(xa.x, ca.x, d0); d0 = fmaf(xa.y, ca.y, d0);
                        d0 = fmaf(xa.z, ca.z, d0); d0 = fmaf(xa.w, ca.w, d0);
                    }
                    float d = fmaf(-2.f, d0, CC[k]);
                    if (d < bd || (d == bd && k < bk)) { bd = d; bk = k; }
                }
            }
            float od = __shfl_xor_sync(0xffffffffu, bd, 1);
            int   ok = __shfl_xor_sync(0xffffffffu, bk, 1);
            if (od < bd || (od == bd && ok < bk)) { bd = od; bk = ok; }

            float* ob = out + (size_t)(n >> 12)*CHW + (n & 4095);
            const float4* cbb = (const float4*)(g_cbn + (size_t)bk*CDIM);
            #pragma unroll
            for (int q = 0; q < 8; ++q) {
                float4 vv = cbb[par*8 + q];
                int c = (par*8 + q) * 4;
                ob[(size_t)(c+0)*HW] = vv.x;
                ob[(size_t)(c+1)*HW] = vv.y;
                ob[(size_t)(c+2)*HW] = vv.z;
                ob[(size_t)(c+3)*HW] = vv.w;
            }
            if (par == 0 && write_idx)
                out[(size_t)NPIX*CDIM + n] = (float)bk;
        }
    }
}

// ---------------------------------------------------------------------------
extern "C" void kernel_launch(void* const* d_in, const int* in_sizes, int n_in,
                              void* d_out, int out_size) {
    const float* x;
    const float* cb;
    if (in_sizes[0] == KCODES*CDIM) {
        cb = (const float*)d_in[0];
        x  = (const float*)d_in[1];
    } else {
        x  = (const float*)d_in[0];
        cb = (const float*)d_in[1];
    }
    float* out = (float*)d_out;

    prep_kernel<<<2, 256>>>(cb);

    cudaFuncSetAttribute(vq_kernel, cudaFuncAttributeMaxDynamicSharedMemorySize, SM_TOTAL);
    int write_idx = (out_size >= NPIX*CDIM + NPIX) ? 1 : 0;
    vq_kernel<<<GRID, 256, SM_TOTAL>>>(x, out, write_idx);
}

// round 9
// speedup vs baseline: 3.1226x; 3.1226x over previous
#include <cuda_runtime.h>
#include <cuda_fp16.h>
#include <math.h>
#include <stdint.h>

#define KCODES 512
#define CDIM   64
#define NPIX   131072
#define HW     4096
#define CHW    262144
#define TILE_M 128
#define NT     (NPIX/TILE_M)    // 1024 tiles
#define GRID   148              // persistent, 1 CTA/SM
#define CBP    72               // fp16 B row pad (144B, conflict-free ldmatrix)
#define XNP    68               // fp32 xn row pad
#define CAP    8
#define MARGIN 4e-3f

// ---------------- smem layout (117248 B) ----------------
#define OFF_B    0                 // 512*72*2 = 73728
#define OFF_XN   73728             // 128*68*4 = 34816
#define OFF_CC   108544            // 512*4 = 2048
#define OFF_INV  110592            // 512*4 = 2048
#define OFF_LIST 112640            // 128*8*4 = 4096
#define OFF_CNT  116736            // 512
#define SM_TOTAL 117248

// ---------------- helpers ----------------
__device__ __forceinline__ uint32_t smem_u32(const void* p) {
    uint32_t a;
    asm("{ .reg .u64 t; cvta.to.shared.u64 t, %1; cvt.u32.u64 %0, t; }" : "=r"(a) : "l"(p));
    return a;
}
__device__ __forceinline__ void ldsm4(uint32_t* r, uint32_t addr) {
    asm volatile("ldmatrix.sync.aligned.m8n8.x4.shared.b16 {%0,%1,%2,%3}, [%4];"
                 : "=r"(r[0]), "=r"(r[1]), "=r"(r[2]), "=r"(r[3]) : "r"(addr));
}
__device__ __forceinline__ void mma16816(float* c, const uint32_t* a,
                                         uint32_t b0, uint32_t b1) {
    asm volatile("mma.sync.aligned.m16n8k16.row.col.f32.f16.f16.f32 "
                 "{%0,%1,%2,%3}, {%4,%5,%6,%7}, {%8,%9}, {%0,%1,%2,%3};"
                 : "+f"(c[0]), "+f"(c[1]), "+f"(c[2]), "+f"(c[3])
                 : "r"(a[0]), "r"(a[1]), "r"(a[2]), "r"(a[3]), "r"(b0), "r"(b1));
}
__device__ __forceinline__ uint32_t h2(float lo, float hi) {
    __half2 v = __floats2half2_rn(lo, hi);
    return *(uint32_t*)&v;
}

// ---------------------------------------------------------------------------
// Single fused persistent kernel.
// Init (once per CTA): normalize codebook -> smem fp16 B + CC + INV.
// Per tile (128 px): normalize x -> XN; fp16 mma.sync prune (batched LDSM,
// ballot-gated pushes); exact fp32 rescore (raw*inv, bit-identical to prep
// semantics); write codes + indices.
// ---------------------------------------------------------------------------
__global__ void __launch_bounds__(256, 1)
vq_kernel(const float* __restrict__ x, const float* __restrict__ cb,
          float* __restrict__ out, int write_idx) {
    extern __shared__ char sm[];
    __half* Bh = (__half*)(sm + OFF_B);
    float*  XN = (float*)(sm + OFF_XN);
    float*  CC = (float*)(sm + OFF_CC);
    float*  IV = (float*)(sm + OFF_INV);
    int*  LIST = (int*)(sm + OFF_LIST);
    int*   CNT = (int*)(sm + OFF_CNT);

    int tid = threadIdx.x, lane = tid & 31, wid = tid >> 5;

    // ---- init: normalize codebook into smem (2 rows per thread) ----
    for (int k = tid; k < KCODES; k += 256) {
        const float4* r4 = (const float4*)(cb + (size_t)k*CDIM);
        float4 buf[16];
        float ss = 0.f;
        #pragma unroll
        for (int q = 0; q < 16; ++q) {
            buf[q] = r4[q];
            ss += buf[q].x*buf[q].x; ss += buf[q].y*buf[q].y;
            ss += buf[q].z*buf[q].z; ss += buf[q].w*buf[q].w;
        }
        float inv = 1.0f / fmaxf(sqrtf(ss), 1e-12f);
        float cc = 0.f;
        #pragma unroll
        for (int q = 0; q < 16; ++q) {
            float v0 = buf[q].x*inv, v1 = buf[q].y*inv;
            float v2 = buf[q].z*inv, v3 = buf[q].w*inv;
            cc += v0*v0; cc += v1*v1; cc += v2*v2; cc += v3*v3;
            *(__half2*)(Bh + k*CBP + q*4)     = __floats2half2_rn(v0, v1);
            *(__half2*)(Bh + k*CBP + q*4 + 2) = __floats2half2_rn(v2, v3);
        }
        CC[k] = cc;
        IV[k] = inv;
    }

    uint32_t smb = smem_u32(sm);
    uint32_t BhB = smb + OFF_B;

    for (int tile = blockIdx.x; tile < NT; tile += GRID) {
        __syncthreads();   // init done / previous tile fully consumed
        if (tid < TILE_M) CNT[tid] = 0;

        // ---- load + normalize x into XN (2 threads per row) ----
        {
            int r = tid >> 1, hc = (tid & 1) * 32;
            int n = tile*TILE_M + r;
            const float* xb = x + (size_t)(n >> 12)*CHW + (n & 4095);
            float v[32];
            float ss = 0.f;
            #pragma unroll
            for (int i = 0; i < 32; ++i) { v[i] = xb[(size_t)(hc+i)*HW]; ss += v[i]*v[i]; }
            ss += __shfl_xor_sync(0xffffffffu, ss, 1);
            float inv = 1.0f / fmaxf(sqrtf(ss), 1e-12f);
            #pragma unroll
            for (int i = 0; i < 32; ++i) XN[r*XNP + hc + i] = v[i] * inv;
        }
        __syncthreads();

        // ---- GEMM prune: warp w rows 16w..16w+15, 8 chunks of 64 codes ----
        {
            int r0 = wid * 16;
            // A fragments from fp32 XN (m16n8k16 row-major layout)
            uint32_t a[4][4];
            {
                int r = lane >> 2, c2 = (lane & 3) * 2;
                const float* xr0 = XN + (r0 + r)*XNP;
                const float* xr8 = xr0 + 8*XNP;
                #pragma unroll
                for (int j = 0; j < 4; ++j) {
                    float2 v0 = *(const float2*)(xr0 + 16*j + c2);
                    float2 v1 = *(const float2*)(xr8 + 16*j + c2);
                    float2 v2 = *(const float2*)(xr0 + 16*j + 8 + c2);
                    float2 v3 = *(const float2*)(xr8 + 16*j + 8 + c2);
                    a[j][0] = h2(v0.x, v0.y);
                    a[j][1] = h2(v1.x, v1.y);
                    a[j][2] = h2(v2.x, v2.y);
                    a[j][3] = h2(v3.x, v3.y);
                }
            }
            int noff = (lane & 7) + ((lane >> 4) << 3);
            int kadd = ((lane >> 3) & 1) << 3;
            int row_lo = r0 + (lane >> 2), row_hi = row_lo + 8;
            float best_lo = 1e30f, best_hi = 1e30f;
            uint32_t baseB = BhB + (uint32_t)((noff*CBP + kadd) * 2);

            for (int chunk = 0; chunk < 8; ++chunk) {
                // batch ALL 16 LDSM first so their latencies overlap
                uint32_t b[4][4][4];   // [j][tp][frag]
                uint32_t cbase = baseB + (uint32_t)(chunk * (64*CBP*2));
                #pragma unroll
                for (int j = 0; j < 4; ++j)
                    #pragma unroll
                    for (int tp = 0; tp < 4; ++tp)
                        ldsm4(b[j][tp], cbase + (uint32_t)(tp*(16*CBP*2) + 32*j));

                float C[8][4];
                #pragma unroll
                for (int t = 0; t < 8; ++t)
                    { C[t][0]=0.f; C[t][1]=0.f; C[t][2]=0.f; C[t][3]=0.f; }
                #pragma unroll
                for (int j = 0; j < 4; ++j)
                    #pragma unroll
                    for (int tp = 0; tp < 4; ++tp) {
                        mma16816(C[2*tp],   a[j], b[j][tp][0], b[j][tp][1]);
                        mma16816(C[2*tp+1], a[j], b[j][tp][2], b[j][tp][3]);
                    }

                int code0base = chunk*64 + 2*(lane & 3);
                float lmin_lo = 1e30f, lmin_hi = 1e30f;
                #pragma unroll
                for (int t = 0; t < 8; ++t) {
                    int c0 = code0base + t*8;
                    float cc0 = CC[c0], cc1 = CC[c0+1];
                    C[t][0] = fmaf(-2.f, C[t][0], cc0);
                    C[t][1] = fmaf(-2.f, C[t][1], cc1);
                    C[t][2] = fmaf(-2.f, C[t][2], cc0);
                    C[t][3] = fmaf(-2.f, C[t][3], cc1);
                    lmin_lo = fminf(lmin_lo, fminf(C[t][0], C[t][1]));
                    lmin_hi = fminf(lmin_hi, fminf(C[t][2], C[t][3]));
                }
                best_lo = fminf(best_lo, lmin_lo);
                best_hi = fminf(best_hi, lmin_hi);
                best_lo = fminf(best_lo, __shfl_xor_sync(0xffffffffu, best_lo, 1));
                best_lo = fminf(best_lo, __shfl_xor_sync(0xffffffffu, best_lo, 2));
                best_hi = fminf(best_hi, __shfl_xor_sync(0xffffffffu, best_hi, 1));
                best_hi = fminf(best_hi, __shfl_xor_sync(0xffffffffu, best_hi, 2));
                float thr_lo = best_lo + MARGIN, thr_hi = best_hi + MARGIN;

                // warp-uniform gate: skip the whole push block when no lane hits
                unsigned any = __ballot_sync(0xffffffffu,
                                (lmin_lo <= thr_lo) || (lmin_hi <= thr_hi));
                if (any) {
                    #pragma unroll
                    for (int t = 0; t < 8; ++t) {
                        int c0 = code0base + t*8;
                        if (C[t][0] <= thr_lo) { int p = atomicAdd(&CNT[row_lo], 1); if (p < CAP) LIST[row_lo*CAP + p] = c0;   }
                        if (C[t][1] <= thr_lo) { int p = atomicAdd(&CNT[row_lo], 1); if (p < CAP) LIST[row_lo*CAP + p] = c0+1; }
                        if (C[t][2] <= thr_hi) { int p = atomicAdd(&CNT[row_hi], 1); if (p < CAP) LIST[row_hi*CAP + p] = c0;   }
                        if (C[t][3] <= thr_hi) { int p = atomicAdd(&CNT[row_hi], 1); if (p < CAP) LIST[row_hi*CAP + p] = c0+1; }
                    }
                }
            }
        }
        __syncthreads();

        // ---- exact fp32 rescore (2 threads/row), codebook = raw*inv ----
        {
            int r = tid >> 1, par = tid & 1;
            int n = tile*TILE_M + r;
            int cn = CNT[r];
            bool ovf = (cn > CAP);
            if (cn > CAP) cn = CAP;

            const float4* x4 = (const float4*)(XN + r*XNP);
            float bd = 1e30f;
            int   bk = 0x7fffffff;

            if (!ovf) {
                for (int i = par; i < cn; i += 2) {
                    int k = LIST[r*CAP + i];
                    float invk = IV[k];
                    const float4* cb4 = (const float4*)(cb + (size_t)k*CDIM);
                    float d0 = 0.f, d1 = 0.f;
                    #pragma unroll
                    for (int q = 0; q < 16; q += 2) {
                        float4 xa = x4[q],   ca = cb4[q];
                        float4 xb2 = x4[q+1], cb2 = cb4[q+1];
                        d0 = fmaf(xa.x, ca.x*invk, d0);  d0 = fmaf(xa.y, ca.y*invk, d0);
                        d0 = fmaf(xa.z, ca.z*invk, d0);  d0 = fmaf(xa.w, ca.w*invk, d0);
                        d1 = fmaf(xb2.x, cb2.x*invk, d1); d1 = fmaf(xb2.y, cb2.y*invk, d1);
                        d1 = fmaf(xb2.z, cb2.z*invk, d1); d1 = fmaf(xb2.w, cb2.w*invk, d1);
                    }
                    float d = fmaf(-2.f, d0 + d1, CC[k]);
                    if (d < bd || (d == bd && k < bk)) { bd = d; bk = k; }
                }
            } else {
                for (int k = par; k < KCODES; k += 2) {
                    float invk = IV[k];
                    const float4* cb4 = (const float4*)(cb + (size_t)k*CDIM);
                    float d0 = 0.f;
                    #pragma unroll
                    for (int q = 0; q < 16; ++q) {
                        float4 xa = x4[q], ca = cb4[q];
                        d0 = fmaf(xa.x, ca.x*invk, d0); d0 = fmaf(xa.y, ca.y*invk, d0);
                        d0 = fmaf(xa.z, ca.z*invk, d0); d0 = fmaf(xa.w, ca.w*invk, d0);
                    }
                    float d = fmaf(-2.f, d0, CC[k]);
                    if (d < bd || (d == bd && k < bk)) { bd = d; bk = k; }
                }
            }
            float od = __shfl_xor_sync(0xffffffffu, bd, 1);
            int   ok = __shfl_xor_sync(0xffffffffu, bk, 1);
            if (od < bd || (od == bd && ok < bk)) { bd = od; bk = ok; }

            // write codes: v = raw*inv (identical fp32 ops as init)
            float invk = IV[bk];
            float* ob = out + (size_t)(n >> 12)*CHW + (n & 4095);
            const float4* cbb = (const float4*)(cb + (size_t)bk*CDIM);
            #pragma unroll
            for (int q = 0; q < 8; ++q) {
                float4 vv = cbb[par*8 + q];
                int c = (par*8 + q) * 4;
                ob[(size_t)(c+0)*HW] = vv.x * invk;
                ob[(size_t)(c+1)*HW] = vv.y * invk;
                ob[(size_t)(c+2)*HW] = vv.z * invk;
                ob[(size_t)(c+3)*HW] = vv.w * invk;
            }
            if (par == 0 && write_idx)
                out[(size_t)NPIX*CDIM + n] = (float)bk;
        }
    }
}

// ---------------------------------------------------------------------------
extern "C" void kernel_launch(void* const* d_in, const int* in_sizes, int n_in,
                              void* d_out, int out_size) {
    const float* x;
    const float* cb;
    if (in_sizes[0] == KCODES*CDIM) {
        cb = (const float*)d_in[0];
        x  = (const float*)d_in[1];
    } else {
        x  = (const float*)d_in[0];
        cb = (const float*)d_in[1];
    }
    float* out = (float*)d_out;

    cudaFuncSetAttribute(vq_kernel, cudaFuncAttributeMaxDynamicSharedMemorySize, SM_TOTAL);
    int write_idx = (out_size >= NPIX*CDIM + NPIX) ? 1 : 0;
    vq_kernel<<<GRID, 256, SM_TOTAL>>>(x, cb, out, write_idx);
}